// round 2
// baseline (speedup 1.0000x reference)
#include <cuda_runtime.h>
#include <cstdint>
#include <cstddef>

// Problem constants
#define BB 2
#define CC 128
#define NN 8192
#define KK 16
#define O1 128
#define O2 256
#define CH3 512
#define EPSF 1e-5f
#define SLOPE 0.2f

// kNN segmentation
#define SEG 8
#define SEGC (NN / SEG)   // 1024 candidates per segment

// ---------------- scratch (device globals; no allocation allowed) ----------------
static __device__ float4 g_pts4[BB * NN];
static __device__ int    g_idx[BB * NN * KK];
static __device__ float  g_pd[(size_t)BB * NN * SEG * KK];  // partial knn dists (sorted asc per seg)
static __device__ int    g_pi[(size_t)BB * NN * SEG * KK];  // partial knn indices
static __device__ float  g_Wmod1[256 * 128];
static __device__ float  g_Wmod2[512 * 128];
static __device__ float  g_G1[(size_t)BB * NN * 256];   // [b][n][0:128 A | 128:256 Bpart]
static __device__ float  g_G2[(size_t)BB * NN * 512];   // [b][n][0:256 A | 256:512 Bpart]
static __device__ float  g_M1[(size_t)BB * NN * 128];   // max over k, layer 1
static __device__ float  g_M2[(size_t)BB * NN * 256];   // max over k, layer 2
static __device__ float  g_X3[(size_t)BB * CH3 * NN];   // concat(x0,x1,x2) channel-major
static __device__ float  g_G3[(size_t)BB * 128 * NN];   // final conv pre-norm, [b][o][n]
static __device__ float  g_sum1[BB * O1], g_sqs1[BB * O1], g_mean1[BB * O1], g_inv1[BB * O1];
static __device__ float  g_sum2[BB * O2], g_sqs2[BB * O2], g_mean2[BB * O2], g_inv2[BB * O2];
static __device__ float  g_mean3[BB * 128], g_inv3[BB * 128];

__device__ __forceinline__ float leakyf(float v) { return v > 0.0f ? v : SLOPE * v; }

// ---------------- prep: modified weights + zero stats ----------------
__global__ void k_prep(const float* __restrict__ W1, const float* __restrict__ W2) {
    int t = blockIdx.x * blockDim.x + threadIdx.x;
    if (t < 256 * 128) {
        int o = t >> 7, c = t & 127;
        if (o < 128) g_Wmod1[t] = W1[o * 256 + c] - W1[o * 256 + 128 + c];
        else         g_Wmod1[t] = W1[(o - 128) * 256 + 128 + c];
    }
    if (t < 512 * 128) {
        int o = t >> 7, c = t & 127;
        if (o < 256) g_Wmod2[t] = W2[o * 256 + c] - W2[o * 256 + 128 + c];
        else         g_Wmod2[t] = W2[(o - 256) * 256 + 128 + c];
    }
    if (t < BB * O1) { g_sum1[t] = 0.0f; g_sqs1[t] = 0.0f; }
    if (t < BB * O2) { g_sum2[t] = 0.0f; g_sqs2[t] = 0.0f; }
}

// ---------------- pack points as float4 (x,y,z,|p|^2) ----------------
__global__ void k_pts4(const float* __restrict__ coords) {
    int i = blockIdx.x * blockDim.x + threadIdx.x;
    if (i >= BB * NN) return;
    int b = i >> 13, n = i & (NN - 1);
    const float* base = coords + (size_t)b * 3 * NN;
    float x = base[n], y = base[NN + n], z = base[2 * NN + n];
    g_pts4[i] = make_float4(x, y, z, x * x + y * y + z * z);
}

// ---------------- kNN phase 1: per-(query, segment) partial top-16 ----------------
// grid: (NN/128, SEG, BB), block: 128 threads, one (query, segment) per thread.
__global__ void k_knn_part() {
    __shared__ float4 sp[SEGC];   // 16 KB
    int b = blockIdx.z;
    int seg = blockIdx.y;
    int qi = blockIdx.x * 128 + threadIdx.x;
    int c0 = seg * SEGC;

    // cooperative load of this segment's candidate points
#pragma unroll
    for (int r = 0; r < SEGC / 128; r++)
        sp[r * 128 + threadIdx.x] = g_pts4[b * NN + c0 + r * 128 + threadIdx.x];
    __syncthreads();

    float4 q = g_pts4[b * NN + qi];
    float qx2 = -2.0f * q.x, qy2 = -2.0f * q.y, qz2 = -2.0f * q.z;

    float dk[16]; int ik[16];
    const float INFF = __int_as_float(0x7f800000);
#pragma unroll
    for (int t = 0; t < 16; t++) { dk[t] = INFF; ik[t] = 0; }

#pragma unroll 4
    for (int j = 0; j < SEGC; j++) {
        float4 p = sp[j];
        float d = fmaf(qx2, p.x, p.w);
        d = fmaf(qy2, p.y, d);
        d = fmaf(qz2, p.z, d);
        int jg = c0 + j;
        if (d < dk[15] && jg != qi) {
            // branchless sorted insert (ascending); equal keeps earlier (lower index)
#pragma unroll
            for (int t = 15; t >= 0; --t) {
                float dp = (t > 0) ? dk[t - 1] : -INFF;
                int   ip = (t > 0) ? ik[t - 1] : 0;
                if (dp > d)         { dk[t] = dp; ik[t] = ip; }
                else if (dk[t] > d) { dk[t] = d;  ik[t] = jg; }
            }
        }
    }

    size_t base = (((size_t)b * NN + qi) * SEG + seg) * KK;
#pragma unroll
    for (int t = 0; t < 16; t++) { g_pd[base + t] = dk[t]; g_pi[base + t] = ik[t]; }
}

// ---------------- kNN phase 2: merge SEG sorted lists -> final top-16 ----------------
__global__ void k_knn_merge() {
    int t = blockIdx.x * blockDim.x + threadIdx.x;
    if (t >= BB * NN) return;

    float dk[16]; int ik[16];
    const float INFF = __int_as_float(0x7f800000);
#pragma unroll
    for (int s = 0; s < 16; s++) { dk[s] = INFF; ik[s] = 0; }

    size_t base = (size_t)t * SEG * KK;
    for (int seg = 0; seg < SEG; seg++) {
        size_t sb = base + (size_t)seg * KK;
#pragma unroll 4
        for (int e = 0; e < KK; e++) {
            float d = g_pd[sb + e];
            if (d >= dk[15]) break;   // segment list ascending -> rest can't qualify
            int jg = g_pi[sb + e];
#pragma unroll
            for (int s = 15; s >= 0; --s) {
                float dp = (s > 0) ? dk[s - 1] : -INFF;
                int   ip = (s > 0) ? ik[s - 1] : 0;
                if (dp > d)         { dk[s] = dp; ik[s] = ip; }
                else if (dk[s] > d) { dk[s] = d;  ik[s] = jg; }
            }
        }
    }
    int* out = g_idx + (size_t)t * KK;
#pragma unroll
    for (int s = 0; s < 16; s++) out[s] = ik[s];
}

// ---------------- fp32 tiled GEMM: Out = W[M,Kd] * X[Kd,N], 128x128 tile, 8x8 micro ----------------
// OUTNM: Out[n*M+m] (n-major, for gather layers). else Out[m*N+n].
template <bool OUTNM>
__global__ void k_gemm(const float* __restrict__ W, const float* __restrict__ X,
                       float* __restrict__ Out, int M, int Nn, int Kd,
                       size_t xStride, size_t oStride) {
    __shared__ float Ws[8][128];
    __shared__ float Xs[8][128];
    const float* Xb = X + blockIdx.z * xStride;
    float* Ob = Out + blockIdx.z * oStride;
    int tid = threadIdx.x;
    int tx = tid & 15, ty = tid >> 4;
    int m0 = blockIdx.y * 128, n0 = blockIdx.x * 128;
    float acc[8][8];
#pragma unroll
    for (int i = 0; i < 8; i++)
#pragma unroll
        for (int j = 0; j < 8; j++) acc[i][j] = 0.0f;

    int mm = tid >> 1, kq = (tid & 1) * 4;
    int kk = tid >> 5, nn = (tid & 31) * 4;

    for (int k0 = 0; k0 < Kd; k0 += 8) {
        float4 wv = *(const float4*)&W[(size_t)(m0 + mm) * Kd + k0 + kq];
        float4 xv = *(const float4*)&Xb[(size_t)(k0 + kk) * Nn + n0 + nn];
        __syncthreads();
        Ws[kq + 0][mm] = wv.x; Ws[kq + 1][mm] = wv.y;
        Ws[kq + 2][mm] = wv.z; Ws[kq + 3][mm] = wv.w;
        *(float4*)&Xs[kk][nn] = xv;
        __syncthreads();
#pragma unroll
        for (int k2 = 0; k2 < 8; k2++) {
            float a[8], bv[8];
            *(float4*)(a)     = *(float4*)&Ws[k2][ty * 8];
            *(float4*)(a + 4) = *(float4*)&Ws[k2][ty * 8 + 4];
            *(float4*)(bv)     = *(float4*)&Xs[k2][tx * 8];
            *(float4*)(bv + 4) = *(float4*)&Xs[k2][tx * 8 + 4];
#pragma unroll
            for (int i = 0; i < 8; i++)
#pragma unroll
                for (int j = 0; j < 8; j++) acc[i][j] = fmaf(a[i], bv[j], acc[i][j]);
        }
    }
    if (OUTNM) {
#pragma unroll
        for (int j = 0; j < 8; j++) {
            int n = n0 + tx * 8 + j;
            float v0[4] = { acc[0][j], acc[1][j], acc[2][j], acc[3][j] };
            float v1[4] = { acc[4][j], acc[5][j], acc[6][j], acc[7][j] };
            float* p = &Ob[(size_t)n * M + m0 + ty * 8];
            *(float4*)(p)     = *(float4*)v0;
            *(float4*)(p + 4) = *(float4*)v1;
        }
    } else {
#pragma unroll
        for (int i = 0; i < 8; i++) {
            int m = m0 + ty * 8 + i;
            float* p = &Ob[(size_t)m * Nn + n0 + tx * 8];
            *(float4*)(p)     = *(float4*)&acc[i][0];
            *(float4*)(p + 4) = *(float4*)&acc[i][4];
        }
    }
}

// ---------------- edge layer: y = A[n,o] + B[idx[n,k],o]; max over k + stats ----------------
template <int O>
__global__ void k_edge(const float* __restrict__ G, const int* __restrict__ idx,
                       float* __restrict__ Mout, float* __restrict__ sums,
                       float* __restrict__ sqs) {
    constexpr int NT = 512 / O;
    constexpr int NPB = 64;
    int b = blockIdx.y;
    int n0 = blockIdx.x * NPB;
    int o = threadIdx.x, ty = threadIdx.y;
    float lsum = 0.0f, lsq = 0.0f;
    const float NEGINF = __int_as_float(0xff800000);

    for (int n = n0 + ty; n < n0 + NPB; n += NT) {
        size_t rowb = (size_t)b * NN + n;
        float a = G[rowb * (2 * O) + o];
        const int* I = idx + rowb * KK;
        float mx = NEGINF;
#pragma unroll
        for (int k = 0; k < KK; k++) {
            int j = I[k];
            float v = a + G[((size_t)b * NN + j) * (2 * O) + O + o];
            mx = fmaxf(mx, v);
            lsum += v;
            lsq = fmaf(v, v, lsq);
        }
        Mout[rowb * O + o] = mx;
    }
    __shared__ float s1[512], s2[512];
    s1[ty * O + o] = lsum; s2[ty * O + o] = lsq;
    __syncthreads();
    if (ty == 0) {
        float t1 = lsum, t2 = lsq;
#pragma unroll
        for (int t = 1; t < NT; t++) { t1 += s1[t * O + o]; t2 += s2[t * O + o]; }
        atomicAdd(&sums[b * O + o], t1);
        atomicAdd(&sqs[b * O + o], t2);
    }
}

// ---------------- finalize instance-norm stats ----------------
__global__ void k_finstats(const float* __restrict__ sums, const float* __restrict__ sqs,
                           float* __restrict__ meanv, float* __restrict__ invv,
                           int total, float invcnt) {
    int t = blockIdx.x * blockDim.x + threadIdx.x;
    if (t < total) {
        float m = sums[t] * invcnt;
        float v = sqs[t] * invcnt - m * m;
        meanv[t] = m;
        invv[t] = rsqrtf(v + EPSF);
    }
}

// ---------------- normalize + leaky + transpose [b,n,o] -> X3[b, obase+o, n] ----------------
__global__ void k_normT(const float* __restrict__ Min, const float* __restrict__ meanv,
                        const float* __restrict__ invv, int O, int obase) {
    __shared__ float t[32][33];
    int b = blockIdx.z, n0 = blockIdx.x * 32, o0 = blockIdx.y * 32;
    int tx = threadIdx.x, ty = threadIdx.y;
    int o = o0 + tx;
    float m = meanv[b * O + o], iv = invv[b * O + o];
#pragma unroll
    for (int i = 0; i < 4; i++) {
        int n = n0 + ty + i * 8;
        float v = Min[((size_t)b * NN + n) * O + o];
        t[tx][ty + i * 8] = leakyf((v - m) * iv);
    }
    __syncthreads();
#pragma unroll
    for (int i = 0; i < 4; i++) {
        int ol = ty + i * 8;
        g_X3[((size_t)b * CH3 + obase + o0 + ol) * NN + n0 + tx] = t[ol][tx];
    }
}

// ---------------- copy x0 into X3 rows 0..127 ----------------
__global__ void k_copyx0(const float* __restrict__ feats) {
    size_t t = (size_t)blockIdx.x * blockDim.x + threadIdx.x;
    if (t >= (size_t)BB * CC * NN) return;
    size_t b = t / ((size_t)CC * NN);
    size_t r = t - b * (size_t)CC * NN;
    g_X3[b * (size_t)CH3 * NN + r] = feats[t];
}

// ---------------- final-layer stats (per (b,o) over n) ----------------
__global__ void k_stats3() {
    int bo = blockIdx.x;
    const float* p = g_G3 + (size_t)bo * NN;
    float s = 0.0f, q = 0.0f;
    for (int n = threadIdx.x; n < NN; n += 256) {
        float v = p[n];
        s += v;
        q = fmaf(v, v, q);
    }
    __shared__ float rs[256], rq[256];
    rs[threadIdx.x] = s; rq[threadIdx.x] = q;
    __syncthreads();
    for (int st = 128; st > 0; st >>= 1) {
        if (threadIdx.x < st) { rs[threadIdx.x] += rs[threadIdx.x + st]; rq[threadIdx.x] += rq[threadIdx.x + st]; }
        __syncthreads();
    }
    if (threadIdx.x == 0) {
        float m = rs[0] * (1.0f / NN);
        float v = rq[0] * (1.0f / NN) - m * m;
        g_mean3[bo] = m;
        g_inv3[bo] = rsqrtf(v + EPSF);
    }
}

// ---------------- final normalize + leaky -> output [B,C,N] ----------------
__global__ void k_final(float* __restrict__ out) {
    size_t t = (size_t)blockIdx.x * blockDim.x + threadIdx.x;
    if (t >= (size_t)BB * 128 * NN) return;
    int bo = (int)(t / NN);
    float v = (g_G3[t] - g_mean3[bo]) * g_inv3[bo];
    out[t] = leakyf(v);
}

// ---------------- launch ----------------
extern "C" void kernel_launch(void* const* d_in, const int* in_sizes, int n_in,
                              void* d_out, int out_size) {
    const float* coords = (const float*)d_in[0];
    const float* feats  = (const float*)d_in[1];
    const float* W1     = (const float*)d_in[2];
    const float* W2     = (const float*)d_in[3];
    const float* W3     = (const float*)d_in[4];
    float* out = (float*)d_out;

    float *pG1, *pG2, *pM1, *pM2, *pG3;
    int* pIdx;
    float *pSum1, *pSqs1, *pMean1, *pInv1, *pSum2, *pSqs2, *pMean2, *pInv2;
    cudaGetSymbolAddress((void**)&pG1, g_G1);
    cudaGetSymbolAddress((void**)&pG2, g_G2);
    cudaGetSymbolAddress((void**)&pM1, g_M1);
    cudaGetSymbolAddress((void**)&pM2, g_M2);
    cudaGetSymbolAddress((void**)&pG3, g_G3);
    cudaGetSymbolAddress((void**)&pIdx, g_idx);
    cudaGetSymbolAddress((void**)&pSum1, g_sum1);
    cudaGetSymbolAddress((void**)&pSqs1, g_sqs1);
    cudaGetSymbolAddress((void**)&pMean1, g_mean1);
    cudaGetSymbolAddress((void**)&pInv1, g_inv1);
    cudaGetSymbolAddress((void**)&pSum2, g_sum2);
    cudaGetSymbolAddress((void**)&pSqs2, g_sqs2);
    cudaGetSymbolAddress((void**)&pMean2, g_mean2);
    cudaGetSymbolAddress((void**)&pInv2, g_inv2);
    float *pWmod1, *pWmod2, *pX3;
    cudaGetSymbolAddress((void**)&pWmod1, g_Wmod1);
    cudaGetSymbolAddress((void**)&pWmod2, g_Wmod2);
    cudaGetSymbolAddress((void**)&pX3, g_X3);
    (void)in_sizes; (void)n_in; (void)out_size;

    // prep: Wmod1/Wmod2 + zero stats; pack points; copy x0 into X3
    k_prep<<<256, 256>>>(W1, W2);
    k_pts4<<<(BB * NN + 255) / 256, 256>>>(coords);
    k_copyx0<<<(BB * CC * NN + 255) / 256, 256>>>(feats);

    // kNN: segmented partial top-16 then merge
    k_knn_part<<<dim3(NN / 128, SEG, BB), 128>>>();
    k_knn_merge<<<(BB * NN + 255) / 256, 256>>>();

    // layer 1: GEMM -> edge -> stats -> norm+transpose into X3[128:256]
    k_gemm<true><<<dim3(NN / 128, 256 / 128, BB), 256>>>(
        pWmod1, feats, pG1, 256, NN, 128, (size_t)CC * NN, (size_t)NN * 256);
    k_edge<128><<<dim3(NN / 64, BB), dim3(128, 4)>>>(pG1, pIdx, pM1, pSum1, pSqs1);
    k_finstats<<<1, 256>>>(pSum1, pSqs1, pMean1, pInv1, BB * O1, 1.0f / (NN * KK));
    k_normT<<<dim3(NN / 32, O1 / 32, BB), dim3(32, 8)>>>(pM1, pMean1, pInv1, O1, 128);

    // layer 2: GEMM on x1 -> edge -> stats -> norm+transpose into X3[256:512]
    k_gemm<true><<<dim3(NN / 128, 512 / 128, BB), 256>>>(
        pWmod2, pX3 + (size_t)128 * NN, pG2, 512, NN, 128, (size_t)CH3 * NN, (size_t)NN * 512);
    k_edge<256><<<dim3(NN / 64, BB), dim3(256, 2)>>>(pG2, pIdx, pM2, pSum2, pSqs2);
    k_finstats<<<1, 512>>>(pSum2, pSqs2, pMean2, pInv2, BB * O2, 1.0f / (NN * KK));
    k_normT<<<dim3(NN / 32, O2 / 32, BB), dim3(32, 8)>>>(pM2, pMean2, pInv2, O2, 256);

    // final layer: GEMM (channel-major out) -> per-(b,o) stats -> norm+leaky
    k_gemm<false><<<dim3(NN / 128, 128 / 128, BB), 256>>>(
        W3, pX3, pG3, 128, NN, 512, (size_t)CH3 * NN, (size_t)128 * NN);
    k_stats3<<<BB * 128, 256>>>();
    k_final<<<(BB * 128 * NN + 255) / 256, 256>>>(out);
}

// round 3
// speedup vs baseline: 1.7946x; 1.7946x over previous
#include <cuda_runtime.h>
#include <cstdint>
#include <cstddef>

// Problem constants
#define BB 2
#define CC 128
#define NN 8192
#define KK 16
#define O1 128
#define O2 256
#define CH3 512
#define EPSF 1e-5f
#define SLOPE 0.2f

// ---------------- scratch (device globals; no allocation allowed) ----------------
static __device__ float4 g_pts4[BB * NN];
static __device__ int    g_idx[BB * NN * KK];
static __device__ float  g_Wmod1[256 * 128];
static __device__ float  g_Wmod2[512 * 128];
static __device__ float  g_G1[(size_t)BB * NN * 256];   // [b][n][0:128 A | 128:256 Bpart]
static __device__ float  g_G2[(size_t)BB * NN * 512];   // [b][n][0:256 A | 256:512 Bpart]
static __device__ float  g_M1[(size_t)BB * NN * 128];   // max over k, layer 1
static __device__ float  g_M2[(size_t)BB * NN * 256];   // max over k, layer 2
static __device__ float  g_X3[(size_t)BB * CH3 * NN];   // concat(x0,x1,x2) channel-major
static __device__ float  g_G3[(size_t)BB * 128 * NN];   // final conv pre-norm, [b][o][n]
static __device__ float  g_sum1[BB * O1], g_sqs1[BB * O1], g_mean1[BB * O1], g_inv1[BB * O1];
static __device__ float  g_sum2[BB * O2], g_sqs2[BB * O2], g_mean2[BB * O2], g_inv2[BB * O2];
static __device__ float  g_mean3[BB * 128], g_inv3[BB * 128];

__device__ __forceinline__ float leakyf(float v) { return v > 0.0f ? v : SLOPE * v; }

// ---------------- prep: modified weights + zero stats ----------------
__global__ void k_prep(const float* __restrict__ W1, const float* __restrict__ W2) {
    int t = blockIdx.x * blockDim.x + threadIdx.x;
    if (t < 256 * 128) {
        int o = t >> 7, c = t & 127;
        if (o < 128) g_Wmod1[t] = W1[o * 256 + c] - W1[o * 256 + 128 + c];
        else         g_Wmod1[t] = W1[(o - 128) * 256 + 128 + c];
    }
    if (t < 512 * 128) {
        int o = t >> 7, c = t & 127;
        if (o < 256) g_Wmod2[t] = W2[o * 256 + c] - W2[o * 256 + 128 + c];
        else         g_Wmod2[t] = W2[(o - 256) * 256 + 128 + c];
    }
    if (t < BB * O1) { g_sum1[t] = 0.0f; g_sqs1[t] = 0.0f; }
    if (t < BB * O2) { g_sum2[t] = 0.0f; g_sqs2[t] = 0.0f; }
}

// ---------------- pack points as float4 (x,y,z,|p|^2) ----------------
__global__ void k_pts4(const float* __restrict__ coords) {
    int i = blockIdx.x * blockDim.x + threadIdx.x;
    if (i >= BB * NN) return;
    int b = i >> 13, n = i & (NN - 1);
    const float* base = coords + (size_t)b * 3 * NN;
    float x = base[n], y = base[NN + n], z = base[2 * NN + n];
    g_pts4[i] = make_float4(x, y, z, x * x + y * y + z * z);
}

// ---------------- warp-collective kNN: one query per warp ----------------
// Block: 512 threads = 16 warps = 16 queries. Grid: BB*NN/16 blocks.
// Lanes 0..15 hold the distributed sorted top-16 (ascending). thr = 16th dist.
#define KNN_TS 2048          // candidates per smem tile (32 KB)
#define KNN_WPB 16           // warps (queries) per block

__global__ void __launch_bounds__(KNN_WPB * 32, 2) k_knn() {
    __shared__ float4 sp[KNN_TS];
    const unsigned FULL = 0xFFFFFFFFu;
    int lane = threadIdx.x & 31;
    int wid = threadIdx.x >> 5;
    int gq = blockIdx.x * KNN_WPB + wid;     // global query id
    int b = gq >> 13;                        // 8192 queries per batch
    int qi = gq & (NN - 1);

    float4 q = g_pts4[b * NN + qi];
    float qx2 = -2.0f * q.x, qy2 = -2.0f * q.y, qz2 = -2.0f * q.z;

    const float INFF = __int_as_float(0x7f800000);
    float dcur = INFF;   // lane<16: sorted top-16 distances (ascending by lane)
    int   icur = 0;
    float thr = INFF;    // current 16th-best distance (uniform across warp)

    for (int c0 = 0; c0 < NN; c0 += KNN_TS) {
        __syncthreads();
        // cooperative tile load: 2048 float4 / 512 threads = 4 each
#pragma unroll
        for (int r = 0; r < KNN_TS / (KNN_WPB * 32); r++)
            sp[r * (KNN_WPB * 32) + threadIdx.x] =
                g_pts4[b * NN + c0 + r * (KNN_WPB * 32) + threadIdx.x];
        __syncthreads();

#pragma unroll 4
        for (int t0 = 0; t0 < KNN_TS; t0 += 32) {
            float4 p = sp[t0 + lane];
            float d = fmaf(qx2, p.x, p.w);
            d = fmaf(qy2, p.y, d);
            d = fmaf(qz2, p.z, d);
            int jg = c0 + t0 + lane;
            bool pass = (d < thr) && (jg != qi);
            unsigned m = __ballot_sync(FULL, pass);
            while (m) {
                int src = __ffs(m) - 1;
                m &= m - 1;
                float v = __shfl_sync(FULL, d, src);
                int  vi = __shfl_sync(FULL, jg, src);
                if (v < thr) {   // uniform across warp (thr may have tightened)
                    // stable distributed sorted insert: equal elems stay before new
                    unsigned stay = __ballot_sync(FULL, (lane < 16) && (dcur <= v));
                    int pos = __popc(stay);
                    float pd = __shfl_up_sync(FULL, dcur, 1);
                    int   pi = __shfl_up_sync(FULL, icur, 1);
                    if (lane < 16 && lane >= pos) {
                        dcur = (lane == pos) ? v : pd;
                        icur = (lane == pos) ? vi : pi;
                    }
                    thr = __shfl_sync(FULL, dcur, 15);
                }
            }
        }
    }

    if (lane < 16)
        g_idx[((size_t)b * NN + qi) * KK + lane] = icur;
}

// ---------------- fp32 tiled GEMM: Out = W[M,Kd] * X[Kd,N], 128x128 tile, 8x8 micro ----------------
// OUTNM: Out[n*M+m] (n-major, for gather layers). else Out[m*N+n].
template <bool OUTNM>
__global__ void k_gemm(const float* __restrict__ W, const float* __restrict__ X,
                       float* __restrict__ Out, int M, int Nn, int Kd,
                       size_t xStride, size_t oStride) {
    __shared__ float Ws[8][128];
    __shared__ float Xs[8][128];
    const float* Xb = X + blockIdx.z * xStride;
    float* Ob = Out + blockIdx.z * oStride;
    int tid = threadIdx.x;
    int tx = tid & 15, ty = tid >> 4;
    int m0 = blockIdx.y * 128, n0 = blockIdx.x * 128;
    float acc[8][8];
#pragma unroll
    for (int i = 0; i < 8; i++)
#pragma unroll
        for (int j = 0; j < 8; j++) acc[i][j] = 0.0f;

    int mm = tid >> 1, kq = (tid & 1) * 4;
    int kk = tid >> 5, nn = (tid & 31) * 4;

    for (int k0 = 0; k0 < Kd; k0 += 8) {
        float4 wv = *(const float4*)&W[(size_t)(m0 + mm) * Kd + k0 + kq];
        float4 xv = *(const float4*)&Xb[(size_t)(k0 + kk) * Nn + n0 + nn];
        __syncthreads();
        Ws[kq + 0][mm] = wv.x; Ws[kq + 1][mm] = wv.y;
        Ws[kq + 2][mm] = wv.z; Ws[kq + 3][mm] = wv.w;
        *(float4*)&Xs[kk][nn] = xv;
        __syncthreads();
#pragma unroll
        for (int k2 = 0; k2 < 8; k2++) {
            float a[8], bv[8];
            *(float4*)(a)     = *(float4*)&Ws[k2][ty * 8];
            *(float4*)(a + 4) = *(float4*)&Ws[k2][ty * 8 + 4];
            *(float4*)(bv)     = *(float4*)&Xs[k2][tx * 8];
            *(float4*)(bv + 4) = *(float4*)&Xs[k2][tx * 8 + 4];
#pragma unroll
            for (int i = 0; i < 8; i++)
#pragma unroll
                for (int j = 0; j < 8; j++) acc[i][j] = fmaf(a[i], bv[j], acc[i][j]);
        }
    }
    if (OUTNM) {
#pragma unroll
        for (int j = 0; j < 8; j++) {
            int n = n0 + tx * 8 + j;
            float v0[4] = { acc[0][j], acc[1][j], acc[2][j], acc[3][j] };
            float v1[4] = { acc[4][j], acc[5][j], acc[6][j], acc[7][j] };
            float* p = &Ob[(size_t)n * M + m0 + ty * 8];
            *(float4*)(p)     = *(float4*)v0;
            *(float4*)(p + 4) = *(float4*)v1;
        }
    } else {
#pragma unroll
        for (int i = 0; i < 8; i++) {
            int m = m0 + ty * 8 + i;
            float* p = &Ob[(size_t)m * Nn + n0 + tx * 8];
            *(float4*)(p)     = *(float4*)&acc[i][0];
            *(float4*)(p + 4) = *(float4*)&acc[i][4];
        }
    }
}

// ---------------- edge layer: y = A[n,o] + B[idx[n,k],o]; max over k + stats ----------------
template <int O>
__global__ void k_edge(const float* __restrict__ G, const int* __restrict__ idx,
                       float* __restrict__ Mout, float* __restrict__ sums,
                       float* __restrict__ sqs) {
    constexpr int NT = 512 / O;
    constexpr int NPB = 64;
    int b = blockIdx.y;
    int n0 = blockIdx.x * NPB;
    int o = threadIdx.x, ty = threadIdx.y;
    float lsum = 0.0f, lsq = 0.0f;
    const float NEGINF = __int_as_float(0xff800000);

    for (int n = n0 + ty; n < n0 + NPB; n += NT) {
        size_t rowb = (size_t)b * NN + n;
        float a = G[rowb * (2 * O) + o];
        const int* I = idx + rowb * KK;
        float mx = NEGINF;
#pragma unroll
        for (int k = 0; k < KK; k++) {
            int j = I[k];
            float v = a + G[((size_t)b * NN + j) * (2 * O) + O + o];
            mx = fmaxf(mx, v);
            lsum += v;
            lsq = fmaf(v, v, lsq);
        }
        Mout[rowb * O + o] = mx;
    }
    __shared__ float s1[512], s2[512];
    s1[ty * O + o] = lsum; s2[ty * O + o] = lsq;
    __syncthreads();
    if (ty == 0) {
        float t1 = lsum, t2 = lsq;
#pragma unroll
        for (int t = 1; t < NT; t++) { t1 += s1[t * O + o]; t2 += s2[t * O + o]; }
        atomicAdd(&sums[b * O + o], t1);
        atomicAdd(&sqs[b * O + o], t2);
    }
}

// ---------------- finalize instance-norm stats ----------------
__global__ void k_finstats(const float* __restrict__ sums, const float* __restrict__ sqs,
                           float* __restrict__ meanv, float* __restrict__ invv,
                           int total, float invcnt) {
    int t = blockIdx.x * blockDim.x + threadIdx.x;
    if (t < total) {
        float m = sums[t] * invcnt;
        float v = sqs[t] * invcnt - m * m;
        meanv[t] = m;
        invv[t] = rsqrtf(v + EPSF);
    }
}

// ---------------- normalize + leaky + transpose [b,n,o] -> X3[b, obase+o, n] ----------------
__global__ void k_normT(const float* __restrict__ Min, const float* __restrict__ meanv,
                        const float* __restrict__ invv, int O, int obase) {
    __shared__ float t[32][33];
    int b = blockIdx.z, n0 = blockIdx.x * 32, o0 = blockIdx.y * 32;
    int tx = threadIdx.x, ty = threadIdx.y;
    int o = o0 + tx;
    float m = meanv[b * O + o], iv = invv[b * O + o];
#pragma unroll
    for (int i = 0; i < 4; i++) {
        int n = n0 + ty + i * 8;
        float v = Min[((size_t)b * NN + n) * O + o];
        t[tx][ty + i * 8] = leakyf((v - m) * iv);
    }
    __syncthreads();
#pragma unroll
    for (int i = 0; i < 4; i++) {
        int ol = ty + i * 8;
        g_X3[((size_t)b * CH3 + obase + o0 + ol) * NN + n0 + tx] = t[ol][tx];
    }
}

// ---------------- copy x0 into X3 rows 0..127 ----------------
__global__ void k_copyx0(const float* __restrict__ feats) {
    size_t t = (size_t)blockIdx.x * blockDim.x + threadIdx.x;
    if (t >= (size_t)BB * CC * NN) return;
    size_t b = t / ((size_t)CC * NN);
    size_t r = t - b * (size_t)CC * NN;
    g_X3[b * (size_t)CH3 * NN + r] = feats[t];
}

// ---------------- final-layer stats (per (b,o) over n) ----------------
__global__ void k_stats3() {
    int bo = blockIdx.x;
    const float* p = g_G3 + (size_t)bo * NN;
    float s = 0.0f, q = 0.0f;
    for (int n = threadIdx.x; n < NN; n += 256) {
        float v = p[n];
        s += v;
        q = fmaf(v, v, q);
    }
    __shared__ float rs[256], rq[256];
    rs[threadIdx.x] = s; rq[threadIdx.x] = q;
    __syncthreads();
    for (int st = 128; st > 0; st >>= 1) {
        if (threadIdx.x < st) { rs[threadIdx.x] += rs[threadIdx.x + st]; rq[threadIdx.x] += rq[threadIdx.x + st]; }
        __syncthreads();
    }
    if (threadIdx.x == 0) {
        float m = rs[0] * (1.0f / NN);
        float v = rq[0] * (1.0f / NN) - m * m;
        g_mean3[bo] = m;
        g_inv3[bo] = rsqrtf(v + EPSF);
    }
}

// ---------------- final normalize + leaky -> output [B,C,N] ----------------
__global__ void k_final(float* __restrict__ out) {
    size_t t = (size_t)blockIdx.x * blockDim.x + threadIdx.x;
    if (t >= (size_t)BB * 128 * NN) return;
    int bo = (int)(t / NN);
    float v = (g_G3[t] - g_mean3[bo]) * g_inv3[bo];
    out[t] = leakyf(v);
}

// ---------------- launch ----------------
extern "C" void kernel_launch(void* const* d_in, const int* in_sizes, int n_in,
                              void* d_out, int out_size) {
    const float* coords = (const float*)d_in[0];
    const float* feats  = (const float*)d_in[1];
    const float* W1     = (const float*)d_in[2];
    const float* W2     = (const float*)d_in[3];
    const float* W3     = (const float*)d_in[4];
    float* out = (float*)d_out;

    float *pG1, *pG2, *pM1, *pM2, *pG3;
    int* pIdx;
    float *pSum1, *pSqs1, *pMean1, *pInv1, *pSum2, *pSqs2, *pMean2, *pInv2;
    cudaGetSymbolAddress((void**)&pG1, g_G1);
    cudaGetSymbolAddress((void**)&pG2, g_G2);
    cudaGetSymbolAddress((void**)&pM1, g_M1);
    cudaGetSymbolAddress((void**)&pM2, g_M2);
    cudaGetSymbolAddress((void**)&pG3, g_G3);
    cudaGetSymbolAddress((void**)&pIdx, g_idx);
    cudaGetSymbolAddress((void**)&pSum1, g_sum1);
    cudaGetSymbolAddress((void**)&pSqs1, g_sqs1);
    cudaGetSymbolAddress((void**)&pMean1, g_mean1);
    cudaGetSymbolAddress((void**)&pInv1, g_inv1);
    cudaGetSymbolAddress((void**)&pSum2, g_sum2);
    cudaGetSymbolAddress((void**)&pSqs2, g_sqs2);
    cudaGetSymbolAddress((void**)&pMean2, g_mean2);
    cudaGetSymbolAddress((void**)&pInv2, g_inv2);
    float *pWmod1, *pWmod2, *pX3;
    cudaGetSymbolAddress((void**)&pWmod1, g_Wmod1);
    cudaGetSymbolAddress((void**)&pWmod2, g_Wmod2);
    cudaGetSymbolAddress((void**)&pX3, g_X3);
    (void)in_sizes; (void)n_in; (void)out_size;

    // prep: Wmod1/Wmod2 + zero stats; pack points; copy x0 into X3
    k_prep<<<256, 256>>>(W1, W2);
    k_pts4<<<(BB * NN + 255) / 256, 256>>>(coords);
    k_copyx0<<<(BB * CC * NN + 255) / 256, 256>>>(feats);

    // warp-collective kNN: one query per warp
    k_knn<<<BB * NN / KNN_WPB, KNN_WPB * 32>>>();

    // layer 1: GEMM -> edge -> stats -> norm+transpose into X3[128:256]
    k_gemm<true><<<dim3(NN / 128, 256 / 128, BB), 256>>>(
        pWmod1, feats, pG1, 256, NN, 128, (size_t)CC * NN, (size_t)NN * 256);
    k_edge<128><<<dim3(NN / 64, BB), dim3(128, 4)>>>(pG1, pIdx, pM1, pSum1, pSqs1);
    k_finstats<<<1, 256>>>(pSum1, pSqs1, pMean1, pInv1, BB * O1, 1.0f / (NN * KK));
    k_normT<<<dim3(NN / 32, O1 / 32, BB), dim3(32, 8)>>>(pM1, pMean1, pInv1, O1, 128);

    // layer 2: GEMM on x1 -> edge -> stats -> norm+transpose into X3[256:512]
    k_gemm<true><<<dim3(NN / 128, 512 / 128, BB), 256>>>(
        pWmod2, pX3 + (size_t)128 * NN, pG2, 512, NN, 128, (size_t)CH3 * NN, (size_t)NN * 512);
    k_edge<256><<<dim3(NN / 64, BB), dim3(256, 2)>>>(pG2, pIdx, pM2, pSum2, pSqs2);
    k_finstats<<<1, 512>>>(pSum2, pSqs2, pMean2, pInv2, BB * O2, 1.0f / (NN * KK));
    k_normT<<<dim3(NN / 32, O2 / 32, BB), dim3(32, 8)>>>(pM2, pMean2, pInv2, O2, 256);

    // final layer: GEMM (channel-major out) -> per-(b,o) stats -> norm+leaky
    k_gemm<false><<<dim3(NN / 128, 128 / 128, BB), 256>>>(
        W3, pX3, pG3, 128, NN, 512, (size_t)CH3 * NN, (size_t)128 * NN);
    k_stats3<<<BB * 128, 256>>>();
    k_final<<<(BB * 128 * NN + 255) / 256, 256>>>(out);
}

// round 4
// speedup vs baseline: 1.8518x; 1.0319x over previous
#include <cuda_runtime.h>
#include <cstdint>
#include <cstddef>

// Problem constants
#define BB 2
#define CC 128
#define NN 8192
#define KK 16
#define O1 128
#define O2 256
#define CH3 512
#define EPSF 1e-5f
#define SLOPE 0.2f

typedef unsigned long long ull;

// ---------------- scratch (device globals; no allocation allowed) ----------------
static __device__ float4 g_pts4[BB * NN];
static __device__ int    g_idx[BB * NN * KK];
static __device__ float  g_Wmod1[256 * 128];
static __device__ float  g_Wmod2[512 * 128];
static __device__ float  g_G1[(size_t)BB * NN * 256];   // [b][n][0:128 A | 128:256 Bpart]
static __device__ float  g_G2[(size_t)BB * NN * 512];   // [b][n][0:256 A | 256:512 Bpart]
static __device__ float  g_M1[(size_t)BB * NN * 128];   // max over k, layer 1
static __device__ float  g_M2[(size_t)BB * NN * 256];   // max over k, layer 2
static __device__ float  g_X3[(size_t)BB * CH3 * NN];   // concat(x0,x1,x2) channel-major
static __device__ float  g_G3[(size_t)BB * 128 * NN];   // final conv pre-norm, [b][o][n]
static __device__ float  g_sum1[BB * O1], g_sqs1[BB * O1], g_mean1[BB * O1], g_inv1[BB * O1];
static __device__ float  g_sum2[BB * O2], g_sqs2[BB * O2], g_mean2[BB * O2], g_inv2[BB * O2];
static __device__ float  g_mean3[BB * 128], g_inv3[BB * 128];

__device__ __forceinline__ float leakyf(float v) { return v > 0.0f ? v : SLOPE * v; }

// packed f32x2 helpers (Blackwell: fma.rn.f32x2 — 2 fp32 FMA per issue)
__device__ __forceinline__ ull dup2(float x) {
    ull r;
    asm("mov.b64 %0, {%1, %1};" : "=l"(r) : "f"(x));
    return r;
}
__device__ __forceinline__ void fma2(ull& d, ull a, ull b) {
    asm("fma.rn.f32x2 %0, %1, %2, %0;" : "+l"(d) : "l"(a), "l"(b));
}
__device__ __forceinline__ void unpack2(ull v, float& lo, float& hi) {
    asm("mov.b64 {%0, %1}, %2;" : "=f"(lo), "=f"(hi) : "l"(v));
}

// ---------------- prep: modified weights + zero stats ----------------
__global__ void k_prep(const float* __restrict__ W1, const float* __restrict__ W2) {
    int t = blockIdx.x * blockDim.x + threadIdx.x;
    if (t < 256 * 128) {
        int o = t >> 7, c = t & 127;
        if (o < 128) g_Wmod1[t] = W1[o * 256 + c] - W1[o * 256 + 128 + c];
        else         g_Wmod1[t] = W1[(o - 128) * 256 + 128 + c];
    }
    if (t < 512 * 128) {
        int o = t >> 7, c = t & 127;
        if (o < 256) g_Wmod2[t] = W2[o * 256 + c] - W2[o * 256 + 128 + c];
        else         g_Wmod2[t] = W2[(o - 256) * 256 + 128 + c];
    }
    if (t < BB * O1) { g_sum1[t] = 0.0f; g_sqs1[t] = 0.0f; }
    if (t < BB * O2) { g_sum2[t] = 0.0f; g_sqs2[t] = 0.0f; }
}

// ---------------- pack points as float4 (x,y,z,|p|^2) ----------------
__global__ void k_pts4(const float* __restrict__ coords) {
    int i = blockIdx.x * blockDim.x + threadIdx.x;
    if (i >= BB * NN) return;
    int b = i >> 13, n = i & (NN - 1);
    const float* base = coords + (size_t)b * 3 * NN;
    float x = base[n], y = base[NN + n], z = base[2 * NN + n];
    g_pts4[i] = make_float4(x, y, z, x * x + y * y + z * z);
}

// ---------------- warp-collective kNN: 4 queries per warp ----------------
// Block: 256 threads = 8 warps = 32 queries. Grid: BB*NN/32 blocks.
// Per query: lanes 0..15 hold distributed sorted top-16 (ascending); thr = 16th.
#define KNN_TS 2048          // candidates per smem tile (32 KB)
#define KNN_WPB 8
#define KNN_QPW 4

__global__ void __launch_bounds__(KNN_WPB * 32, 4) k_knn() {
    __shared__ float4 sp[KNN_TS];
    const unsigned FULL = 0xFFFFFFFFu;
    int lane = threadIdx.x & 31;
    int wid = threadIdx.x >> 5;
    int gq0 = (blockIdx.x * KNN_WPB + wid) * KNN_QPW;  // first of 4 queries
    int b = gq0 >> 13;
    int qi0 = gq0 & (NN - 1);

    // distribute 4 query coords to all lanes
    float4 myq = g_pts4[b * NN + qi0 + (lane & 3)];
    float qx2[KNN_QPW], qy2[KNN_QPW], qz2[KNN_QPW];
    int qid[KNN_QPW];
#pragma unroll
    for (int j = 0; j < KNN_QPW; j++) {
        qx2[j] = -2.0f * __shfl_sync(FULL, myq.x, j);
        qy2[j] = -2.0f * __shfl_sync(FULL, myq.y, j);
        qz2[j] = -2.0f * __shfl_sync(FULL, myq.z, j);
        qid[j] = qi0 + j;
    }

    const float INFF = __int_as_float(0x7f800000);
    float dcur[KNN_QPW]; int icur[KNN_QPW]; float thr[KNN_QPW];
#pragma unroll
    for (int j = 0; j < KNN_QPW; j++) { dcur[j] = INFF; icur[j] = 0; thr[j] = INFF; }

    for (int c0 = 0; c0 < NN; c0 += KNN_TS) {
        __syncthreads();
#pragma unroll
        for (int r = 0; r < KNN_TS / (KNN_WPB * 32); r++)
            sp[r * (KNN_WPB * 32) + threadIdx.x] =
                g_pts4[b * NN + c0 + r * (KNN_WPB * 32) + threadIdx.x];
        __syncthreads();

#pragma unroll 2
        for (int t0 = 0; t0 < KNN_TS; t0 += 32) {
            float4 p = sp[t0 + lane];
            int jg = c0 + t0 + lane;
#pragma unroll
            for (int j = 0; j < KNN_QPW; j++) {
                float d = fmaf(qx2[j], p.x, p.w);
                d = fmaf(qy2[j], p.y, d);
                d = fmaf(qz2[j], p.z, d);
                bool pass = (d < thr[j]) && (jg != qid[j]);
                unsigned m = __ballot_sync(FULL, pass);
                while (m) {
                    int src = __ffs(m) - 1;
                    m &= m - 1;
                    float v = __shfl_sync(FULL, d, src);
                    int  vi = __shfl_sync(FULL, jg, src);
                    if (v < thr[j]) {
                        // stable distributed sorted insert (equal keeps earlier)
                        unsigned stay = __ballot_sync(FULL, (lane < 16) && (dcur[j] <= v));
                        int pos = __popc(stay);
                        float pd = __shfl_up_sync(FULL, dcur[j], 1);
                        int   pi = __shfl_up_sync(FULL, icur[j], 1);
                        if (lane < 16 && lane >= pos) {
                            dcur[j] = (lane == pos) ? v : pd;
                            icur[j] = (lane == pos) ? vi : pi;
                        }
                        thr[j] = __shfl_sync(FULL, dcur[j], 15);
                    }
                }
            }
        }
    }

    if (lane < 16) {
#pragma unroll
        for (int j = 0; j < KNN_QPW; j++)
            g_idx[((size_t)b * NN + qi0 + j) * KK + lane] = icur[j];
    }
}

// ---------------- fp32 GEMM with packed f32x2 FMA + double-buffered smem ----------------
// Out = W[M,Kd] * X[Kd,N], 128x128 tile, 8x8 micro per thread (256 threads).
// OUTNM: Out[n*M+m] (n-major). else Out[m*N+n].
template <bool OUTNM>
__global__ void __launch_bounds__(256, 2) k_gemm(
        const float* __restrict__ W, const float* __restrict__ X,
        float* __restrict__ Out, int M, int Nn, int Kd,
        size_t xStride, size_t oStride) {
    __shared__ float Ws[2][8][128];
    __shared__ float Xs[2][8][128];
    const float* Xb = X + blockIdx.z * xStride;
    float* Ob = Out + blockIdx.z * oStride;
    int tid = threadIdx.x;
    int tx = tid & 15, ty = tid >> 4;
    int m0 = blockIdx.y * 128, n0 = blockIdx.x * 128;

    ull acc2[8][4];
#pragma unroll
    for (int i = 0; i < 8; i++)
#pragma unroll
        for (int jp = 0; jp < 4; jp++) acc2[i][jp] = 0ull;

    int mm = tid >> 1, kq = (tid & 1) * 4;
    int kk = tid >> 5, nn = (tid & 31) * 4;

    // preload slab 0 into buffer 0
    {
        float4 wv = *(const float4*)&W[(size_t)(m0 + mm) * Kd + kq];
        float4 xv = *(const float4*)&Xb[(size_t)kk * Nn + n0 + nn];
        Ws[0][kq + 0][mm] = wv.x; Ws[0][kq + 1][mm] = wv.y;
        Ws[0][kq + 2][mm] = wv.z; Ws[0][kq + 3][mm] = wv.w;
        *(float4*)&Xs[0][kk][nn] = xv;
    }
    __syncthreads();

    int p = 0;
    for (int k0 = 0; k0 < Kd; k0 += 8) {
        // prefetch next slab (global -> regs)
        float4 wn, xn;
        bool more = (k0 + 8) < Kd;
        if (more) {
            wn = *(const float4*)&W[(size_t)(m0 + mm) * Kd + k0 + 8 + kq];
            xn = *(const float4*)&Xb[(size_t)(k0 + 8 + kk) * Nn + n0 + nn];
        }
        // compute from buffer p
#pragma unroll
        for (int k2 = 0; k2 < 8; k2++) {
            float4 av0 = *(const float4*)&Ws[p][k2][ty * 8];
            float4 av1 = *(const float4*)&Ws[p][k2][ty * 8 + 4];
            ulonglong2 bq0 = *(const ulonglong2*)&Xs[p][k2][tx * 8];
            ulonglong2 bq1 = *(const ulonglong2*)&Xs[p][k2][tx * 8 + 4];
            ull b2[4] = { bq0.x, bq0.y, bq1.x, bq1.y };
            float af[8] = { av0.x, av0.y, av0.z, av0.w, av1.x, av1.y, av1.z, av1.w };
#pragma unroll
            for (int i = 0; i < 8; i++) {
                ull a2 = dup2(af[i]);
#pragma unroll
                for (int jp = 0; jp < 4; jp++) fma2(acc2[i][jp], a2, b2[jp]);
            }
        }
        // store prefetched slab into the other buffer
        if (more) {
            int q = p ^ 1;
            Ws[q][kq + 0][mm] = wn.x; Ws[q][kq + 1][mm] = wn.y;
            Ws[q][kq + 2][mm] = wn.z; Ws[q][kq + 3][mm] = wn.w;
            *(float4*)&Xs[q][kk][nn] = xn;
            __syncthreads();
            p = q;
        }
    }

    // unpack accumulators
    float acc[8][8];
#pragma unroll
    for (int i = 0; i < 8; i++)
#pragma unroll
        for (int jp = 0; jp < 4; jp++)
            unpack2(acc2[i][jp], acc[i][2 * jp], acc[i][2 * jp + 1]);

    if (OUTNM) {
#pragma unroll
        for (int j = 0; j < 8; j++) {
            int n = n0 + tx * 8 + j;
            float v0[4] = { acc[0][j], acc[1][j], acc[2][j], acc[3][j] };
            float v1[4] = { acc[4][j], acc[5][j], acc[6][j], acc[7][j] };
            float* pp = &Ob[(size_t)n * M + m0 + ty * 8];
            *(float4*)(pp)     = *(float4*)v0;
            *(float4*)(pp + 4) = *(float4*)v1;
        }
    } else {
#pragma unroll
        for (int i = 0; i < 8; i++) {
            int m = m0 + ty * 8 + i;
            float* pp = &Ob[(size_t)m * Nn + n0 + tx * 8];
            *(float4*)(pp)     = *(float4*)&acc[i][0];
            *(float4*)(pp + 4) = *(float4*)&acc[i][4];
        }
    }
}

// ---------------- edge layer: y = A[n,o] + B[idx[n,k],o]; max over k + stats ----------------
template <int O>
__global__ void k_edge(const float* __restrict__ G, const int* __restrict__ idx,
                       float* __restrict__ Mout, float* __restrict__ sums,
                       float* __restrict__ sqs) {
    constexpr int NT = 512 / O;
    constexpr int NPB = 64;
    int b = blockIdx.y;
    int n0 = blockIdx.x * NPB;
    int o = threadIdx.x, ty = threadIdx.y;
    float lsum = 0.0f, lsq = 0.0f;
    const float NEGINF = __int_as_float(0xff800000);

    for (int n = n0 + ty; n < n0 + NPB; n += NT) {
        size_t rowb = (size_t)b * NN + n;
        float a = G[rowb * (2 * O) + o];
        const int* I = idx + rowb * KK;
        float mx = NEGINF;
#pragma unroll
        for (int k = 0; k < KK; k++) {
            int j = I[k];
            float v = a + G[((size_t)b * NN + j) * (2 * O) + O + o];
            mx = fmaxf(mx, v);
            lsum += v;
            lsq = fmaf(v, v, lsq);
        }
        Mout[rowb * O + o] = mx;
    }
    __shared__ float s1[512], s2[512];
    s1[ty * O + o] = lsum; s2[ty * O + o] = lsq;
    __syncthreads();
    if (ty == 0) {
        float t1 = lsum, t2 = lsq;
#pragma unroll
        for (int t = 1; t < NT; t++) { t1 += s1[t * O + o]; t2 += s2[t * O + o]; }
        atomicAdd(&sums[b * O + o], t1);
        atomicAdd(&sqs[b * O + o], t2);
    }
}

// ---------------- finalize instance-norm stats ----------------
__global__ void k_finstats(const float* __restrict__ sums, const float* __restrict__ sqs,
                           float* __restrict__ meanv, float* __restrict__ invv,
                           int total, float invcnt) {
    int t = blockIdx.x * blockDim.x + threadIdx.x;
    if (t < total) {
        float m = sums[t] * invcnt;
        float v = sqs[t] * invcnt - m * m;
        meanv[t] = m;
        invv[t] = rsqrtf(v + EPSF);
    }
}

// ---------------- normalize + leaky + transpose [b,n,o] -> X3[b, obase+o, n] ----------------
__global__ void k_normT(const float* __restrict__ Min, const float* __restrict__ meanv,
                        const float* __restrict__ invv, int O, int obase) {
    __shared__ float t[32][33];
    int b = blockIdx.z, n0 = blockIdx.x * 32, o0 = blockIdx.y * 32;
    int tx = threadIdx.x, ty = threadIdx.y;
    int o = o0 + tx;
    float m = meanv[b * O + o], iv = invv[b * O + o];
#pragma unroll
    for (int i = 0; i < 4; i++) {
        int n = n0 + ty + i * 8;
        float v = Min[((size_t)b * NN + n) * O + o];
        t[tx][ty + i * 8] = leakyf((v - m) * iv);
    }
    __syncthreads();
#pragma unroll
    for (int i = 0; i < 4; i++) {
        int ol = ty + i * 8;
        g_X3[((size_t)b * CH3 + obase + o0 + ol) * NN + n0 + tx] = t[ol][tx];
    }
}

// ---------------- copy x0 into X3 rows 0..127 ----------------
__global__ void k_copyx0(const float* __restrict__ feats) {
    size_t t = (size_t)blockIdx.x * blockDim.x + threadIdx.x;
    if (t >= (size_t)BB * CC * NN) return;
    size_t b = t / ((size_t)CC * NN);
    size_t r = t - b * (size_t)CC * NN;
    g_X3[b * (size_t)CH3 * NN + r] = feats[t];
}

// ---------------- final-layer stats (per (b,o) over n) ----------------
__global__ void k_stats3() {
    int bo = blockIdx.x;
    const float* p = g_G3 + (size_t)bo * NN;
    float s = 0.0f, q = 0.0f;
    for (int n = threadIdx.x; n < NN; n += 256) {
        float v = p[n];
        s += v;
        q = fmaf(v, v, q);
    }
    __shared__ float rs[256], rq[256];
    rs[threadIdx.x] = s; rq[threadIdx.x] = q;
    __syncthreads();
    for (int st = 128; st > 0; st >>= 1) {
        if (threadIdx.x < st) { rs[threadIdx.x] += rs[threadIdx.x + st]; rq[threadIdx.x] += rq[threadIdx.x + st]; }
        __syncthreads();
    }
    if (threadIdx.x == 0) {
        float m = rs[0] * (1.0f / NN);
        float v = rq[0] * (1.0f / NN) - m * m;
        g_mean3[bo] = m;
        g_inv3[bo] = rsqrtf(v + EPSF);
    }
}

// ---------------- final normalize + leaky -> output [B,C,N] ----------------
__global__ void k_final(float* __restrict__ out) {
    size_t t = (size_t)blockIdx.x * blockDim.x + threadIdx.x;
    if (t >= (size_t)BB * 128 * NN) return;
    int bo = (int)(t / NN);
    float v = (g_G3[t] - g_mean3[bo]) * g_inv3[bo];
    out[t] = leakyf(v);
}

// ---------------- launch ----------------
extern "C" void kernel_launch(void* const* d_in, const int* in_sizes, int n_in,
                              void* d_out, int out_size) {
    const float* coords = (const float*)d_in[0];
    const float* feats  = (const float*)d_in[1];
    const float* W1     = (const float*)d_in[2];
    const float* W2     = (const float*)d_in[3];
    const float* W3     = (const float*)d_in[4];
    float* out = (float*)d_out;

    float *pG1, *pG2, *pM1, *pM2, *pG3;
    int* pIdx;
    float *pSum1, *pSqs1, *pMean1, *pInv1, *pSum2, *pSqs2, *pMean2, *pInv2;
    cudaGetSymbolAddress((void**)&pG1, g_G1);
    cudaGetSymbolAddress((void**)&pG2, g_G2);
    cudaGetSymbolAddress((void**)&pM1, g_M1);
    cudaGetSymbolAddress((void**)&pM2, g_M2);
    cudaGetSymbolAddress((void**)&pG3, g_G3);
    cudaGetSymbolAddress((void**)&pIdx, g_idx);
    cudaGetSymbolAddress((void**)&pSum1, g_sum1);
    cudaGetSymbolAddress((void**)&pSqs1, g_sqs1);
    cudaGetSymbolAddress((void**)&pMean1, g_mean1);
    cudaGetSymbolAddress((void**)&pInv1, g_inv1);
    cudaGetSymbolAddress((void**)&pSum2, g_sum2);
    cudaGetSymbolAddress((void**)&pSqs2, g_sqs2);
    cudaGetSymbolAddress((void**)&pMean2, g_mean2);
    cudaGetSymbolAddress((void**)&pInv2, g_inv2);
    float *pWmod1, *pWmod2, *pX3;
    cudaGetSymbolAddress((void**)&pWmod1, g_Wmod1);
    cudaGetSymbolAddress((void**)&pWmod2, g_Wmod2);
    cudaGetSymbolAddress((void**)&pX3, g_X3);
    (void)in_sizes; (void)n_in; (void)out_size;

    // prep: Wmod1/Wmod2 + zero stats; pack points; copy x0 into X3
    k_prep<<<256, 256>>>(W1, W2);
    k_pts4<<<(BB * NN + 255) / 256, 256>>>(coords);
    k_copyx0<<<(BB * CC * NN + 255) / 256, 256>>>(feats);

    // warp-collective kNN: 4 queries per warp
    k_knn<<<BB * NN / (KNN_WPB * KNN_QPW), KNN_WPB * 32>>>();

    // layer 1: GEMM -> edge -> stats -> norm+transpose into X3[128:256]
    k_gemm<true><<<dim3(NN / 128, 256 / 128, BB), 256>>>(
        pWmod1, feats, pG1, 256, NN, 128, (size_t)CC * NN, (size_t)NN * 256);
    k_edge<128><<<dim3(NN / 64, BB), dim3(128, 4)>>>(pG1, pIdx, pM1, pSum1, pSqs1);
    k_finstats<<<1, 256>>>(pSum1, pSqs1, pMean1, pInv1, BB * O1, 1.0f / (NN * KK));
    k_normT<<<dim3(NN / 32, O1 / 32, BB), dim3(32, 8)>>>(pM1, pMean1, pInv1, O1, 128);

    // layer 2: GEMM on x1 -> edge -> stats -> norm+transpose into X3[256:512]
    k_gemm<true><<<dim3(NN / 128, 512 / 128, BB), 256>>>(
        pWmod2, pX3 + (size_t)128 * NN, pG2, 512, NN, 128, (size_t)CH3 * NN, (size_t)NN * 512);
    k_edge<256><<<dim3(NN / 64, BB), dim3(256, 2)>>>(pG2, pIdx, pM2, pSum2, pSqs2);
    k_finstats<<<1, 512>>>(pSum2, pSqs2, pMean2, pInv2, BB * O2, 1.0f / (NN * KK));
    k_normT<<<dim3(NN / 32, O2 / 32, BB), dim3(32, 8)>>>(pM2, pMean2, pInv2, O2, 256);

    // final layer: GEMM (channel-major out) -> per-(b,o) stats -> norm+leaky
    k_gemm<false><<<dim3(NN / 128, 128 / 128, BB), 256>>>(
        W3, pX3, pG3, 128, NN, 512, (size_t)CH3 * NN, (size_t)128 * NN);
    k_stats3<<<BB * 128, 256>>>();
    k_final<<<(BB * 128 * NN + 255) / 256, 256>>>(out);
}